// round 13
// baseline (speedup 1.0000x reference)
#include <cuda_runtime.h>

#define NN 50000
#define NE 640000
#define NR 8
#define D1 128
#define D2 64

// Scratch (allocation-free rule: __device__ globals)
__device__ float g_rel1[(size_t)NR * NN * D1]; // 204.8 MB
__device__ float g_rel2[(size_t)NR * NN * D2]; // 102.4 MB
__device__ float g_h1[(size_t)NN * D1];        // 25.6 MB
__device__ int   g_cnt[NN];
__device__ int   g_off[NN + 1];
__device__ int   g_cur[NN];
__device__ int   g_keys[NE];                   // et*NN + src, CSR-by-dst order

// ---------------- tf32 helpers ----------------
__device__ __forceinline__ unsigned f2tf32(float x) {
    unsigned r;
    asm("cvt.rna.tf32.f32 %0, %1;" : "=r"(r) : "f"(x));
    return r;
}

__device__ __forceinline__ void mma_tf32(float4& d, const unsigned a[4],
                                         unsigned b0, unsigned b1) {
    asm volatile(
        "mma.sync.aligned.m16n8k8.row.col.f32.tf32.tf32.f32 "
        "{%0,%1,%2,%3}, {%4,%5,%6,%7}, {%8,%9}, {%0,%1,%2,%3};\n"
        : "+f"(d.x), "+f"(d.y), "+f"(d.z), "+f"(d.w)
        : "r"(a[0]), "r"(a[1]), "r"(a[2]), "r"(a[3]), "r"(b0), "r"(b1));
}

// C[z] = (relu?)(A) @ W[z] (+ bias) with tf32x3 (hi*hi + hi*lo + lo*hi)
// A:[NN,128] fp32, W:[Z,128,DOUT], C:[Z,NN,DOUT]
template<int DOUT, bool RELU_IN, bool ADD_BIAS>
__global__ void __launch_bounds__(256) gemm_tf32(
    const float* __restrict__ A,
    const float* __restrict__ Wall,
    const float* __restrict__ bias,
    float* __restrict__ Call)
{
    constexpr int BM = 128, BK = 16;
    constexpr int AS = 20;         // padded A stride: (4*row+k)%32 bijective per warp
    constexpr int WS = DOUT + 8;   // padded W stride: (8k+n)%32 bijective per warp
    constexpr int NT = DOUT / 8;   // 16 or 8 n-tiles per warp

    __shared__ float As[BM][AS];
    __shared__ float Wh[BK][WS];
    __shared__ float Wl[BK][WS];

    const float* W = Wall + (size_t)blockIdx.z * 128 * DOUT;
    float* C = Call + (size_t)blockIdx.z * (size_t)NN * DOUT;

    const int tid  = threadIdx.x;
    const int warp = tid >> 5, lane = tid & 31;
    const int grp  = lane >> 2, tig = lane & 3;
    const int rowBase = blockIdx.x * BM;

    float4 acc[NT];
    #pragma unroll
    for (int nt = 0; nt < NT; nt++) acc[nt] = make_float4(0.f, 0.f, 0.f, 0.f);

    for (int k0 = 0; k0 < 128; k0 += BK) {
        // --- A tile: BM x BK = 512 float4, 2 per thread ---
        #pragma unroll
        for (int t = 0; t < 2; t++) {
            int idx = tid + t * 256;
            int r = idx >> 2, kq = idx & 3;
            int grow = rowBase + r;
            float4 v = make_float4(0.f, 0.f, 0.f, 0.f);
            if (grow < NN)
                v = *(const float4*)(A + (size_t)grow * 128 + k0 + kq * 4);
            if (RELU_IN) {
                v.x = fmaxf(v.x, 0.f); v.y = fmaxf(v.y, 0.f);
                v.z = fmaxf(v.z, 0.f); v.w = fmaxf(v.w, 0.f);
            }
            *(float4*)(&As[r][kq * 4]) = v;
        }
        // --- W tile: BK x DOUT, pre-split into tf32 hi/lo planes ---
        constexpr int WF = (BK * DOUT / 4) / 256;  // 2 (DOUT=128) or 1 (DOUT=64)
        #pragma unroll
        for (int t = 0; t < WF; t++) {
            int idx = tid + t * 256;
            int kk = idx / (DOUT / 4);
            int oq = idx % (DOUT / 4);
            float4 v = *(const float4*)(W + (size_t)(k0 + kk) * DOUT + oq * 4);
            float* wh = &Wh[kk][oq * 4];
            float* wl = &Wl[kk][oq * 4];
            float h;
            h = __uint_as_float(f2tf32(v.x)); wh[0] = h; wl[0] = __uint_as_float(f2tf32(v.x - h));
            h = __uint_as_float(f2tf32(v.y)); wh[1] = h; wl[1] = __uint_as_float(f2tf32(v.y - h));
            h = __uint_as_float(f2tf32(v.z)); wh[2] = h; wl[2] = __uint_as_float(f2tf32(v.z - h));
            h = __uint_as_float(f2tf32(v.w)); wh[3] = h; wl[3] = __uint_as_float(f2tf32(v.w - h));
        }
        __syncthreads();

        #pragma unroll
        for (int ks = 0; ks < BK; ks += 8) {
            const int r0 = warp * 16 + grp;
            float x0 = As[r0    ][ks + tig];
            float x1 = As[r0 + 8][ks + tig];
            float x2 = As[r0    ][ks + tig + 4];
            float x3 = As[r0 + 8][ks + tig + 4];
            unsigned ah[4], al[4];
            ah[0] = f2tf32(x0); al[0] = f2tf32(x0 - __uint_as_float(ah[0]));
            ah[1] = f2tf32(x1); al[1] = f2tf32(x1 - __uint_as_float(ah[1]));
            ah[2] = f2tf32(x2); al[2] = f2tf32(x2 - __uint_as_float(ah[2]));
            ah[3] = f2tf32(x3); al[3] = f2tf32(x3 - __uint_as_float(ah[3]));
            #pragma unroll
            for (int nt = 0; nt < NT; nt++) {
                const int n = nt * 8 + grp;
                unsigned bh0 = __float_as_uint(Wh[ks + tig    ][n]);
                unsigned bh1 = __float_as_uint(Wh[ks + tig + 4][n]);
                unsigned bl0 = __float_as_uint(Wl[ks + tig    ][n]);
                unsigned bl1 = __float_as_uint(Wl[ks + tig + 4][n]);
                mma_tf32(acc[nt], ah, bh0, bh1);
                mma_tf32(acc[nt], ah, bl0, bl1);
                mma_tf32(acc[nt], al, bh0, bh1);
            }
        }
        __syncthreads();
    }

    // --- epilogue: c0/c1 -> row r0, c2/c3 -> row r0+8, cols tig*2, tig*2+1 ---
    const int r0 = rowBase + warp * 16 + grp;
    #pragma unroll
    for (int nt = 0; nt < NT; nt++) {
        int col = nt * 8 + tig * 2;
        float2 v0 = make_float2(acc[nt].x, acc[nt].y);
        float2 v1 = make_float2(acc[nt].z, acc[nt].w);
        if (ADD_BIAS) {
            float b0v = bias[col], b1v = bias[col + 1];
            v0.x += b0v; v0.y += b1v;
            v1.x += b0v; v1.y += b1v;
        }
        if (r0 < NN)
            *(float2*)(C + (size_t)r0 * DOUT + col) = v0;
        if (r0 + 8 < NN)
            *(float2*)(C + (size_t)(r0 + 8) * DOUT + col) = v1;
    }
}

// ---------------- CSR build (by dst) ----------------
__global__ void __launch_bounds__(256) zero_cnt_kernel(int* __restrict__ cnt) {
    int i = blockIdx.x * 256 + threadIdx.x;
    if (i < NN) cnt[i] = 0;
}

__global__ void __launch_bounds__(256) hist_kernel(const int* __restrict__ dst,
                                                   int* __restrict__ cnt) {
    int e = blockIdx.x * 256 + threadIdx.x;
    if (e < NE) atomicAdd(&cnt[dst[e]], 1);
}

__global__ void __launch_bounds__(1024) scan_kernel(const int* __restrict__ cnt,
                                                    int* __restrict__ off,
                                                    int* __restrict__ cur) {
    __shared__ int part[1024];
    const int t = threadIdx.x;
    constexpr int C = (NN + 1023) / 1024;  // 49
    const int base = t * C;
    int s = 0;
    for (int i = 0; i < C; i++) {
        int idx = base + i;
        if (idx < NN) s += cnt[idx];
    }
    part[t] = s;
    __syncthreads();
    // Hillis-Steele inclusive scan
    for (int d = 1; d < 1024; d <<= 1) {
        int v = (t >= d) ? part[t - d] : 0;
        __syncthreads();
        part[t] += v;
        __syncthreads();
    }
    int run = (t == 0) ? 0 : part[t - 1];
    for (int i = 0; i < C; i++) {
        int idx = base + i;
        if (idx < NN) {
            off[idx] = run;
            cur[idx] = run;
            run += cnt[idx];
        }
    }
    if (t == 1023) off[NN] = run;  // == NE
}

__global__ void __launch_bounds__(256) fill_kernel(
    const int* __restrict__ src, const int* __restrict__ dst,
    const int* __restrict__ et, int* __restrict__ cur,
    int* __restrict__ keys)
{
    int e = blockIdx.x * 256 + threadIdx.x;
    if (e >= NE) return;
    int pos = atomicAdd(&cur[dst[e]], 1);
    keys[pos] = et[e] * NN + src[e];
}

// ---------------- atomic-free gather-aggregate ----------------
// out[d,:] += sum over incoming edges of rel[key(e), :]
template<int DOUT>
__global__ void __launch_bounds__(256) gather_kernel(
    const int* __restrict__ off, const int* __restrict__ keys,
    const float* __restrict__ rel, float* __restrict__ out)
{
    constexpr int LPN = DOUT / 4;   // lanes per node: 32 or 16
    constexpr int NPW = 32 / LPN;   // nodes per warp:  1 or 2
    int warp = (blockIdx.x * 256 + threadIdx.x) >> 5;
    int lane = threadIdx.x & 31;
    int d = warp * NPW + lane / LPN;
    if (d >= NN) return;
    int l = lane % LPN;
    int beg = off[d], end = off[d + 1];
    float4 acc = make_float4(0.f, 0.f, 0.f, 0.f);
    for (int j = beg; j < end; j++) {
        int key = keys[j];
        float4 v = *(const float4*)(rel + (size_t)key * DOUT + l * 4);
        acc.x += v.x; acc.y += v.y; acc.z += v.z; acc.w += v.w;
    }
    float* o = out + (size_t)d * DOUT + l * 4;
    float4 ov = *(float4*)o;
    ov.x += acc.x; ov.y += acc.y; ov.z += acc.z; ov.w += acc.w;
    *(float4*)o = ov;
}

extern "C" void kernel_launch(void* const* d_in, const int* in_sizes, int n_in,
                              void* d_out, int out_size)
{
    const float* feat = (const float*)d_in[0];
    const int*   src  = (const int*)d_in[1];
    const int*   dst  = (const int*)d_in[2];
    const int*   et   = (const int*)d_in[3];
    const float* W1   = (const float*)d_in[4];
    const float* W1s  = (const float*)d_in[5];
    const float* b1   = (const float*)d_in[6];
    const float* W2   = (const float*)d_in[7];
    const float* W2s  = (const float*)d_in[8];
    const float* b2   = (const float*)d_in[9];
    float* out = (float*)d_out;

    float *rel1, *rel2, *h1;
    int *cnt, *off, *cur, *keys;
    cudaGetSymbolAddress((void**)&rel1, g_rel1);
    cudaGetSymbolAddress((void**)&rel2, g_rel2);
    cudaGetSymbolAddress((void**)&h1,   g_h1);
    cudaGetSymbolAddress((void**)&cnt,  g_cnt);
    cudaGetSymbolAddress((void**)&off,  g_off);
    cudaGetSymbolAddress((void**)&cur,  g_cur);
    cudaGetSymbolAddress((void**)&keys, g_keys);

    dim3 blk(256);
    const int gm = (NN + 127) / 128;  // 391

    // CSR-by-dst build (shared by both layers)
    zero_cnt_kernel<<<(NN + 255) / 256, blk>>>(cnt);
    hist_kernel<<<(NE + 255) / 256, blk>>>(dst, cnt);
    scan_kernel<<<1, 1024>>>(cnt, off, cur);
    fill_kernel<<<(NE + 255) / 256, blk>>>(src, dst, et, cur, keys);

    // Layer 1
    gemm_tf32<128, false, false><<<dim3(gm, 1, NR), blk>>>(feat, W1,  nullptr, rel1);
    gemm_tf32<128, false, true ><<<dim3(gm, 1, 1 ), blk>>>(feat, W1s, b1,      h1);
    gather_kernel<128><<<(NN * 32 + 255) / 256, blk>>>(off, keys, rel1, h1);

    // Layer 2 (ReLU fused on reads of h1)
    gemm_tf32<64, true, false><<<dim3(gm, 1, NR), blk>>>(h1, W2,  nullptr, rel2);
    gemm_tf32<64, true, true ><<<dim3(gm, 1, 1 ), blk>>>(h1, W2s, b2,      out);
    gather_kernel<64><<<(NN * 16 + 255) / 256, blk>>>(off, keys, rel2, out);
}

// round 14
// speedup vs baseline: 1.1226x; 1.1226x over previous
#include <cuda_runtime.h>
#include <cuda_fp16.h>

#define NN 50000
#define NE 640000
#define NR 8
#define D1 128
#define D2 64

// Scratch (allocation-free rule: __device__ globals)
__device__ __half g_rel1[(size_t)NR * NN * D1]; // 102.4 MB (fp16)
__device__ __half g_rel2[(size_t)NR * NN * D2]; //  51.2 MB (fp16, L2-resident)
__device__ float  g_h1[(size_t)NN * D1];        //  25.6 MB
__device__ int    g_cnt[NN];
__device__ int    g_off[NN + 1];
__device__ int    g_cur[NN];
__device__ int    g_keys[NE];                   // et*NN + src, CSR-by-dst order

// ---------------- tf32 helpers ----------------
__device__ __forceinline__ unsigned f2tf32(float x) {
    unsigned r;
    asm("cvt.rna.tf32.f32 %0, %1;" : "=r"(r) : "f"(x));
    return r;
}

__device__ __forceinline__ void mma_tf32(float4& d, const unsigned a[4],
                                         unsigned b0, unsigned b1) {
    asm volatile(
        "mma.sync.aligned.m16n8k8.row.col.f32.tf32.tf32.f32 "
        "{%0,%1,%2,%3}, {%4,%5,%6,%7}, {%8,%9}, {%0,%1,%2,%3};\n"
        : "+f"(d.x), "+f"(d.y), "+f"(d.z), "+f"(d.w)
        : "r"(a[0]), "r"(a[1]), "r"(a[2]), "r"(a[3]), "r"(b0), "r"(b1));
}

// C[z] = (relu?)(A) @ W[z] (+ bias) with tf32x3 (hi*hi + hi*lo + lo*hi)
// A:[NN,128] fp32, W:[Z,128,DOUT], C:[Z,NN,DOUT] (OutT = float or __half)
template<int DOUT, bool RELU_IN, bool ADD_BIAS, typename OutT>
__global__ void __launch_bounds__(256) gemm_tf32(
    const float* __restrict__ A,
    const float* __restrict__ Wall,
    const float* __restrict__ bias,
    OutT* __restrict__ Call)
{
    constexpr int BM = 128, BK = 16;
    constexpr int AS = 20;         // padded A stride: conflict-free fragment reads
    constexpr int WS = DOUT + 8;   // padded W stride
    constexpr int NT = DOUT / 8;   // 16 or 8 n-tiles per warp

    __shared__ float As[BM][AS];
    __shared__ float Wh[BK][WS];
    __shared__ float Wl[BK][WS];

    const float* W = Wall + (size_t)blockIdx.z * 128 * DOUT;
    OutT* C = Call + (size_t)blockIdx.z * (size_t)NN * DOUT;

    const int tid  = threadIdx.x;
    const int warp = tid >> 5, lane = tid & 31;
    const int grp  = lane >> 2, tig = lane & 3;
    const int rowBase = blockIdx.x * BM;

    float4 acc[NT];
    #pragma unroll
    for (int nt = 0; nt < NT; nt++) acc[nt] = make_float4(0.f, 0.f, 0.f, 0.f);

    for (int k0 = 0; k0 < 128; k0 += BK) {
        // --- A tile: BM x BK = 512 float4, 2 per thread ---
        #pragma unroll
        for (int t = 0; t < 2; t++) {
            int idx = tid + t * 256;
            int r = idx >> 2, kq = idx & 3;
            int grow = rowBase + r;
            float4 v = make_float4(0.f, 0.f, 0.f, 0.f);
            if (grow < NN)
                v = *(const float4*)(A + (size_t)grow * 128 + k0 + kq * 4);
            if (RELU_IN) {
                v.x = fmaxf(v.x, 0.f); v.y = fmaxf(v.y, 0.f);
                v.z = fmaxf(v.z, 0.f); v.w = fmaxf(v.w, 0.f);
            }
            *(float4*)(&As[r][kq * 4]) = v;
        }
        // --- W tile: BK x DOUT, pre-split into tf32 hi/lo planes ---
        constexpr int WF = (BK * DOUT / 4) / 256;  // 2 (DOUT=128) or 1 (DOUT=64)
        #pragma unroll
        for (int t = 0; t < WF; t++) {
            int idx = tid + t * 256;
            int kk = idx / (DOUT / 4);
            int oq = idx % (DOUT / 4);
            float4 v = *(const float4*)(W + (size_t)(k0 + kk) * DOUT + oq * 4);
            float* wh = &Wh[kk][oq * 4];
            float* wl = &Wl[kk][oq * 4];
            float h;
            h = __uint_as_float(f2tf32(v.x)); wh[0] = h; wl[0] = __uint_as_float(f2tf32(v.x - h));
            h = __uint_as_float(f2tf32(v.y)); wh[1] = h; wl[1] = __uint_as_float(f2tf32(v.y - h));
            h = __uint_as_float(f2tf32(v.z)); wh[2] = h; wl[2] = __uint_as_float(f2tf32(v.z - h));
            h = __uint_as_float(f2tf32(v.w)); wh[3] = h; wl[3] = __uint_as_float(f2tf32(v.w - h));
        }
        __syncthreads();

        #pragma unroll
        for (int ks = 0; ks < BK; ks += 8) {
            const int r0 = warp * 16 + grp;
            float x0 = As[r0    ][ks + tig];
            float x1 = As[r0 + 8][ks + tig];
            float x2 = As[r0    ][ks + tig + 4];
            float x3 = As[r0 + 8][ks + tig + 4];
            unsigned ah[4], al[4];
            ah[0] = f2tf32(x0); al[0] = f2tf32(x0 - __uint_as_float(ah[0]));
            ah[1] = f2tf32(x1); al[1] = f2tf32(x1 - __uint_as_float(ah[1]));
            ah[2] = f2tf32(x2); al[2] = f2tf32(x2 - __uint_as_float(ah[2]));
            ah[3] = f2tf32(x3); al[3] = f2tf32(x3 - __uint_as_float(ah[3]));
            #pragma unroll
            for (int nt = 0; nt < NT; nt++) {
                const int n = nt * 8 + grp;
                unsigned bh0 = __float_as_uint(Wh[ks + tig    ][n]);
                unsigned bh1 = __float_as_uint(Wh[ks + tig + 4][n]);
                unsigned bl0 = __float_as_uint(Wl[ks + tig    ][n]);
                unsigned bl1 = __float_as_uint(Wl[ks + tig + 4][n]);
                mma_tf32(acc[nt], ah, bh0, bh1);
                mma_tf32(acc[nt], ah, bl0, bl1);
                mma_tf32(acc[nt], al, bh0, bh1);
            }
        }
        __syncthreads();
    }

    // --- epilogue: c0/c1 -> row r0, c2/c3 -> row r0+8, cols tig*2, tig*2+1 ---
    const int r0 = rowBase + warp * 16 + grp;
    #pragma unroll
    for (int nt = 0; nt < NT; nt++) {
        int col = nt * 8 + tig * 2;
        float2 v0 = make_float2(acc[nt].x, acc[nt].y);
        float2 v1 = make_float2(acc[nt].z, acc[nt].w);
        if (ADD_BIAS) {
            float b0v = bias[col], b1v = bias[col + 1];
            v0.x += b0v; v0.y += b1v;
            v1.x += b0v; v1.y += b1v;
        }
        if (sizeof(OutT) == 2) {
            __half2* Crow0 = (__half2*)(C + (size_t)r0 * DOUT);
            __half2* Crow1 = (__half2*)(C + (size_t)(r0 + 8) * DOUT);
            if (r0 < NN)     Crow0[col >> 1] = __floats2half2_rn(v0.x, v0.y);
            if (r0 + 8 < NN) Crow1[col >> 1] = __floats2half2_rn(v1.x, v1.y);
        } else {
            if (r0 < NN)
                *(float2*)((float*)C + (size_t)r0 * DOUT + col) = v0;
            if (r0 + 8 < NN)
                *(float2*)((float*)C + (size_t)(r0 + 8) * DOUT + col) = v1;
        }
    }
}

// ---------------- CSR build (by dst) ----------------
__global__ void __launch_bounds__(256) zero_cnt_kernel(int* __restrict__ cnt) {
    int i = blockIdx.x * 256 + threadIdx.x;
    if (i < NN) cnt[i] = 0;
}

__global__ void __launch_bounds__(256) hist_kernel(const int* __restrict__ dst,
                                                   int* __restrict__ cnt) {
    int e = blockIdx.x * 256 + threadIdx.x;
    if (e < NE) atomicAdd(&cnt[dst[e]], 1);
}

__global__ void __launch_bounds__(1024) scan_kernel(const int* __restrict__ cnt,
                                                    int* __restrict__ off,
                                                    int* __restrict__ cur) {
    __shared__ int part[1024];
    const int t = threadIdx.x;
    constexpr int C = (NN + 1023) / 1024;  // 49
    const int base = t * C;
    int s = 0;
    for (int i = 0; i < C; i++) {
        int idx = base + i;
        if (idx < NN) s += cnt[idx];
    }
    part[t] = s;
    __syncthreads();
    for (int d = 1; d < 1024; d <<= 1) {
        int v = (t >= d) ? part[t - d] : 0;
        __syncthreads();
        part[t] += v;
        __syncthreads();
    }
    int run = (t == 0) ? 0 : part[t - 1];
    for (int i = 0; i < C; i++) {
        int idx = base + i;
        if (idx < NN) {
            off[idx] = run;
            cur[idx] = run;
            run += cnt[idx];
        }
    }
    if (t == 1023) off[NN] = run;  // == NE
}

__global__ void __launch_bounds__(256) fill_kernel(
    const int* __restrict__ src, const int* __restrict__ dst,
    const int* __restrict__ et, int* __restrict__ cur,
    int* __restrict__ keys)
{
    int e = blockIdx.x * 256 + threadIdx.x;
    if (e >= NE) return;
    int pos = atomicAdd(&cur[dst[e]], 1);
    keys[pos] = et[e] * NN + src[e];
}

// ---------------- atomic-free gather-aggregate (fp16 messages) ----------------
// out[d,:] += sum over incoming edges of rel[key(e), :]   (fp32 accumulation)
template<int DOUT>
__global__ void __launch_bounds__(256) gather_h_kernel(
    const int* __restrict__ off, const int* __restrict__ keys,
    const __half* __restrict__ rel, float* __restrict__ out)
{
    constexpr int LPN = DOUT / 8;   // lanes per node: 16 (D=128) or 8 (D=64)
    constexpr int NPW = 32 / LPN;   // nodes per warp:  2 or 4
    int warp = (blockIdx.x * 256 + threadIdx.x) >> 5;
    int lane = threadIdx.x & 31;
    int d = warp * NPW + lane / LPN;
    if (d >= NN) return;
    int l = lane % LPN;
    int beg = off[d], end = off[d + 1];
    float acc[8];
    #pragma unroll
    for (int i = 0; i < 8; i++) acc[i] = 0.f;
    for (int j = beg; j < end; j++) {
        int key = keys[j];
        float4 v = ((const float4*)(rel + (size_t)key * DOUT))[l];  // 8 halves
        const __half2* h2 = (const __half2*)&v;
        #pragma unroll
        for (int i = 0; i < 4; i++) {
            float2 f = __half22float2(h2[i]);
            acc[2 * i]     += f.x;
            acc[2 * i + 1] += f.y;
        }
    }
    float* o = out + (size_t)d * DOUT + l * 8;
    float4 a0 = *(float4*)o;
    float4 a1 = *(float4*)(o + 4);
    a0.x += acc[0]; a0.y += acc[1]; a0.z += acc[2]; a0.w += acc[3];
    a1.x += acc[4]; a1.y += acc[5]; a1.z += acc[6]; a1.w += acc[7];
    *(float4*)o = a0;
    *(float4*)(o + 4) = a1;
}

extern "C" void kernel_launch(void* const* d_in, const int* in_sizes, int n_in,
                              void* d_out, int out_size)
{
    const float* feat = (const float*)d_in[0];
    const int*   src  = (const int*)d_in[1];
    const int*   dst  = (const int*)d_in[2];
    const int*   et   = (const int*)d_in[3];
    const float* W1   = (const float*)d_in[4];
    const float* W1s  = (const float*)d_in[5];
    const float* b1   = (const float*)d_in[6];
    const float* W2   = (const float*)d_in[7];
    const float* W2s  = (const float*)d_in[8];
    const float* b2   = (const float*)d_in[9];
    float* out = (float*)d_out;

    __half *rel1, *rel2;
    float *h1;
    int *cnt, *off, *cur, *keys;
    cudaGetSymbolAddress((void**)&rel1, g_rel1);
    cudaGetSymbolAddress((void**)&rel2, g_rel2);
    cudaGetSymbolAddress((void**)&h1,   g_h1);
    cudaGetSymbolAddress((void**)&cnt,  g_cnt);
    cudaGetSymbolAddress((void**)&off,  g_off);
    cudaGetSymbolAddress((void**)&cur,  g_cur);
    cudaGetSymbolAddress((void**)&keys, g_keys);

    // One-time infra (streams/events are not device memory; created on the
    // eager correctness call, reused under capture as fork/join deps).
    static cudaStream_t s2 = nullptr;
    static cudaEvent_t evFork = nullptr, evJoin = nullptr;
    if (!s2) {
        cudaStreamCreateWithFlags(&s2, cudaStreamNonBlocking);
        cudaEventCreateWithFlags(&evFork, cudaEventDisableTiming);
        cudaEventCreateWithFlags(&evJoin, cudaEventDisableTiming);
    }

    dim3 blk(256);
    const int gm = (NN + 127) / 128;  // 391

    // --- fork: CSR-by-dst build on side stream, hidden behind rel1 GEMM ---
    cudaEventRecord(evFork, 0);
    cudaStreamWaitEvent(s2, evFork, 0);
    zero_cnt_kernel<<<(NN + 255) / 256, blk, 0, s2>>>(cnt);
    hist_kernel<<<(NE + 255) / 256, blk, 0, s2>>>(dst, cnt);
    scan_kernel<<<1, 1024, 0, s2>>>(cnt, off, cur);
    fill_kernel<<<(NE + 255) / 256, blk, 0, s2>>>(src, dst, et, cur, keys);
    cudaEventRecord(evJoin, s2);

    // Layer 1 (rel messages stored fp16)
    gemm_tf32<128, false, false, __half><<<dim3(gm, 1, NR), blk>>>(feat, W1,  nullptr, rel1);
    gemm_tf32<128, false, true,  float ><<<dim3(gm, 1, 1 ), blk>>>(feat, W1s, b1,      h1);
    cudaStreamWaitEvent(0, evJoin, 0);  // join: gather needs CSR
    gather_h_kernel<128><<<(NN * 16 + 255) / 256, blk>>>(off, keys, rel1, h1);

    // Layer 2 (ReLU fused on reads of h1; rel2 fp16, L2-resident)
    gemm_tf32<64, true, false, __half><<<dim3(gm, 1, NR), blk>>>(h1, W2,  nullptr, rel2);
    gemm_tf32<64, true, true,  float ><<<dim3(gm, 1, 1 ), blk>>>(h1, W2s, b2,      out);
    gather_h_kernel<64><<<(NN * 8 + 255) / 256, blk>>>(off, keys, rel2, out);
}

// round 15
// speedup vs baseline: 1.4254x; 1.2698x over previous
#include <cuda_runtime.h>
#include <cuda_fp16.h>

#define NN 50000
#define NE 640000
#define NR 8
#define D1 128
#define D2 64

// Scratch (allocation-free rule: __device__ globals)
__device__ __half g_rel1[(size_t)NR * NN * D1]; // 102.4 MB (fp16)
__device__ __half g_rel2[(size_t)NR * NN * D2]; //  51.2 MB (fp16, L2-resident)
__device__ float  g_h1[(size_t)NN * D1];        //  25.6 MB
__device__ int    g_cnt[NN];
__device__ int    g_off[NN + 1];
__device__ int    g_cur[NN];
__device__ int    g_keys[NE];                   // et*NN + src, CSR-by-dst order

// ---------------- fp16 split helpers ----------------
// (x,y) -> packed half2 hi and half2 lo, pair ordered (low half = first arg)
__device__ __forceinline__ void split2(float x, float y, unsigned& h, unsigned& l) {
    __half2 hh = __floats2half2_rn(x, y);
    float2 hf = __half22float2(hh);
    __half2 ll = __floats2half2_rn(x - hf.x, y - hf.y);
    h = *reinterpret_cast<unsigned*>(&hh);
    l = *reinterpret_cast<unsigned*>(&ll);
}

__device__ __forceinline__ void mma_f16(float4& d, const unsigned a[4],
                                        unsigned b0, unsigned b1) {
    asm volatile(
        "mma.sync.aligned.m16n8k16.row.col.f32.f16.f16.f32 "
        "{%0,%1,%2,%3}, {%4,%5,%6,%7}, {%8,%9}, {%0,%1,%2,%3};\n"
        : "+f"(d.x), "+f"(d.y), "+f"(d.z), "+f"(d.w)
        : "r"(a[0]), "r"(a[1]), "r"(a[2]), "r"(a[3]), "r"(b0), "r"(b1));
}

// C[z] = (relu?)(A) @ W[z] (+ bias) with fp16x3 (hi*hi + hi*lo + lo*hi), fp32 accum
// A:[NN,128] fp32, W:[Z,128,DOUT], C:[Z,NN,DOUT] (OutT = float or __half)
template<int DOUT, bool RELU_IN, bool ADD_BIAS, typename OutT>
__global__ void __launch_bounds__(256) gemm_f16x3(
    const float* __restrict__ A,
    const float* __restrict__ Wall,
    const float* __restrict__ bias,
    OutT* __restrict__ Call)
{
    constexpr int BM = 128, BK = 16;
    constexpr int AS2 = 12;          // uint stride (BK/2=8 + 4 pad): grp*12+tig bijective mod 32
    constexpr int WS2 = DOUT + 8;    // uint stride: (tig*8+grp) bijective mod 32
    constexpr int NT = DOUT / 8;     // 16 or 8 n-tiles per warp

    // A and W stored pre-split as packed half2 pairs along k: [.][j] = (k=2j, k=2j+1)
    __shared__ unsigned Ah2[BM][AS2], Al2[BM][AS2];
    __shared__ unsigned Wh2[BK / 2][WS2], Wl2[BK / 2][WS2];

    const float* W = Wall + (size_t)blockIdx.z * 128 * DOUT;
    OutT* C = Call + (size_t)blockIdx.z * (size_t)NN * DOUT;

    const int tid  = threadIdx.x;
    const int warp = tid >> 5, lane = tid & 31;
    const int grp  = lane >> 2, tig = lane & 3;
    const int rowBase = blockIdx.x * BM;

    float4 acc[NT];
    #pragma unroll
    for (int nt = 0; nt < NT; nt++) acc[nt] = make_float4(0.f, 0.f, 0.f, 0.f);

    for (int k0 = 0; k0 < 128; k0 += BK) {
        // --- A tile: BM x BK, split to fp16 hi/lo at load; 512 float4, 2/thread ---
        #pragma unroll
        for (int t = 0; t < 2; t++) {
            int idx = tid + t * 256;
            int r = idx >> 2, kq = idx & 3;
            int grow = rowBase + r;
            float4 v = make_float4(0.f, 0.f, 0.f, 0.f);
            if (grow < NN)
                v = *(const float4*)(A + (size_t)grow * 128 + k0 + kq * 4);
            if (RELU_IN) {
                v.x = fmaxf(v.x, 0.f); v.y = fmaxf(v.y, 0.f);
                v.z = fmaxf(v.z, 0.f); v.w = fmaxf(v.w, 0.f);
            }
            unsigned h0, l0, h1v, l1v;
            split2(v.x, v.y, h0, l0);
            split2(v.z, v.w, h1v, l1v);
            Ah2[r][kq * 2]     = h0;  Al2[r][kq * 2]     = l0;
            Ah2[r][kq * 2 + 1] = h1v; Al2[r][kq * 2 + 1] = l1v;
        }
        // --- W tile: BK x DOUT, split + pack pairs along k ---
        constexpr int WENT = (BK / 2) * (DOUT / 4);  // 256 (D=128) or 128 (D=64)
        if (WENT >= 256 || tid < WENT) {
            int kk2 = tid / (DOUT / 4);
            int n4  = tid % (DOUT / 4);
            const float* Wr = W + (size_t)(k0 + 2 * kk2) * DOUT + n4 * 4;
            float4 w0 = *(const float4*)Wr;
            float4 w1 = *(const float4*)(Wr + DOUT);
            unsigned h, l;
            split2(w0.x, w1.x, h, l); Wh2[kk2][n4 * 4 + 0] = h; Wl2[kk2][n4 * 4 + 0] = l;
            split2(w0.y, w1.y, h, l); Wh2[kk2][n4 * 4 + 1] = h; Wl2[kk2][n4 * 4 + 1] = l;
            split2(w0.z, w1.z, h, l); Wh2[kk2][n4 * 4 + 2] = h; Wl2[kk2][n4 * 4 + 2] = l;
            split2(w0.w, w1.w, h, l); Wh2[kk2][n4 * 4 + 3] = h; Wl2[kk2][n4 * 4 + 3] = l;
        }
        __syncthreads();

        // --- single K=16 step ---
        const int r0 = warp * 16 + grp;
        unsigned ah[4], al[4];
        ah[0] = Ah2[r0][tig];         ah[1] = Ah2[r0 + 8][tig];
        ah[2] = Ah2[r0][tig + 4];     ah[3] = Ah2[r0 + 8][tig + 4];
        al[0] = Al2[r0][tig];         al[1] = Al2[r0 + 8][tig];
        al[2] = Al2[r0][tig + 4];     al[3] = Al2[r0 + 8][tig + 4];
        #pragma unroll
        for (int nt = 0; nt < NT; nt++) {
            const int n = nt * 8 + grp;
            unsigned bh0 = Wh2[tig][n], bh1 = Wh2[tig + 4][n];
            unsigned bl0 = Wl2[tig][n], bl1 = Wl2[tig + 4][n];
            mma_f16(acc[nt], ah, bh0, bh1);
            mma_f16(acc[nt], ah, bl0, bl1);
            mma_f16(acc[nt], al, bh0, bh1);
        }
        __syncthreads();
    }

    // --- epilogue: c0/c1 -> row r0, c2/c3 -> row r0+8, cols tig*2, tig*2+1 ---
    const int r0 = rowBase + warp * 16 + grp;
    #pragma unroll
    for (int nt = 0; nt < NT; nt++) {
        int col = nt * 8 + tig * 2;
        float2 v0 = make_float2(acc[nt].x, acc[nt].y);
        float2 v1 = make_float2(acc[nt].z, acc[nt].w);
        if (ADD_BIAS) {
            float b0v = bias[col], b1v = bias[col + 1];
            v0.x += b0v; v0.y += b1v;
            v1.x += b0v; v1.y += b1v;
        }
        if (sizeof(OutT) == 2) {
            __half2* Crow0 = (__half2*)(C + (size_t)r0 * DOUT);
            __half2* Crow1 = (__half2*)(C + (size_t)(r0 + 8) * DOUT);
            if (r0 < NN)     Crow0[col >> 1] = __floats2half2_rn(v0.x, v0.y);
            if (r0 + 8 < NN) Crow1[col >> 1] = __floats2half2_rn(v1.x, v1.y);
        } else {
            if (r0 < NN)
                *(float2*)((float*)C + (size_t)r0 * DOUT + col) = v0;
            if (r0 + 8 < NN)
                *(float2*)((float*)C + (size_t)(r0 + 8) * DOUT + col) = v1;
        }
    }
}

// ---------------- CSR build (by dst) ----------------
__global__ void __launch_bounds__(256) zero_cnt_kernel(int* __restrict__ cnt) {
    int i = blockIdx.x * 256 + threadIdx.x;
    if (i < NN) cnt[i] = 0;
}

__global__ void __launch_bounds__(256) hist_kernel(const int* __restrict__ dst,
                                                   int* __restrict__ cnt) {
    int e = blockIdx.x * 256 + threadIdx.x;
    if (e < NE) atomicAdd(&cnt[dst[e]], 1);
}

__global__ void __launch_bounds__(1024) scan_kernel(const int* __restrict__ cnt,
                                                    int* __restrict__ off,
                                                    int* __restrict__ cur) {
    __shared__ int part[1024];
    const int t = threadIdx.x;
    constexpr int C = (NN + 1023) / 1024;  // 49
    const int base = t * C;
    int s = 0;
    for (int i = 0; i < C; i++) {
        int idx = base + i;
        if (idx < NN) s += cnt[idx];
    }
    part[t] = s;
    __syncthreads();
    for (int d = 1; d < 1024; d <<= 1) {
        int v = (t >= d) ? part[t - d] : 0;
        __syncthreads();
        part[t] += v;
        __syncthreads();
    }
    int run = (t == 0) ? 0 : part[t - 1];
    for (int i = 0; i < C; i++) {
        int idx = base + i;
        if (idx < NN) {
            off[idx] = run;
            cur[idx] = run;
            run += cnt[idx];
        }
    }
    if (t == 1023) off[NN] = run;  // == NE
}

__global__ void __launch_bounds__(256) fill_kernel(
    const int* __restrict__ src, const int* __restrict__ dst,
    const int* __restrict__ et, int* __restrict__ cur,
    int* __restrict__ keys)
{
    int e = blockIdx.x * 256 + threadIdx.x;
    if (e >= NE) return;
    int pos = atomicAdd(&cur[dst[e]], 1);
    keys[pos] = et[e] * NN + src[e];
}

// ---------------- atomic-free gather-aggregate (fp16 messages) ----------------
// out[d,:] += sum over incoming edges of rel[key(e), :]   (fp32 accumulation)
template<int DOUT>
__global__ void __launch_bounds__(256) gather_h_kernel(
    const int* __restrict__ off, const int* __restrict__ keys,
    const __half* __restrict__ rel, float* __restrict__ out)
{
    constexpr int LPN = DOUT / 8;   // lanes per node: 16 (D=128) or 8 (D=64)
    constexpr int NPW = 32 / LPN;   // nodes per warp:  2 or 4
    int warp = (blockIdx.x * 256 + threadIdx.x) >> 5;
    int lane = threadIdx.x & 31;
    int d = warp * NPW + lane / LPN;
    if (d >= NN) return;
    int l = lane % LPN;
    int beg = off[d], end = off[d + 1];
    float acc[8];
    #pragma unroll
    for (int i = 0; i < 8; i++) acc[i] = 0.f;
    for (int j = beg; j < end; j++) {
        int key = keys[j];
        float4 v = ((const float4*)(rel + (size_t)key * DOUT))[l];  // 8 halves
        const __half2* h2 = (const __half2*)&v;
        #pragma unroll
        for (int i = 0; i < 4; i++) {
            float2 f = __half22float2(h2[i]);
            acc[2 * i]     += f.x;
            acc[2 * i + 1] += f.y;
        }
    }
    float* o = out + (size_t)d * DOUT + l * 8;
    float4 a0 = *(float4*)o;
    float4 a1 = *(float4*)(o + 4);
    a0.x += acc[0]; a0.y += acc[1]; a0.z += acc[2]; a0.w += acc[3];
    a1.x += acc[4]; a1.y += acc[5]; a1.z += acc[6]; a1.w += acc[7];
    *(float4*)o = a0;
    *(float4*)(o + 4) = a1;
}

extern "C" void kernel_launch(void* const* d_in, const int* in_sizes, int n_in,
                              void* d_out, int out_size)
{
    const float* feat = (const float*)d_in[0];
    const int*   src  = (const int*)d_in[1];
    const int*   dst  = (const int*)d_in[2];
    const int*   et   = (const int*)d_in[3];
    const float* W1   = (const float*)d_in[4];
    const float* W1s  = (const float*)d_in[5];
    const float* b1   = (const float*)d_in[6];
    const float* W2   = (const float*)d_in[7];
    const float* W2s  = (const float*)d_in[8];
    const float* b2   = (const float*)d_in[9];
    float* out = (float*)d_out;

    __half *rel1, *rel2;
    float *h1;
    int *cnt, *off, *cur, *keys;
    cudaGetSymbolAddress((void**)&rel1, g_rel1);
    cudaGetSymbolAddress((void**)&rel2, g_rel2);
    cudaGetSymbolAddress((void**)&h1,   g_h1);
    cudaGetSymbolAddress((void**)&cnt,  g_cnt);
    cudaGetSymbolAddress((void**)&off,  g_off);
    cudaGetSymbolAddress((void**)&cur,  g_cur);
    cudaGetSymbolAddress((void**)&keys, g_keys);

    // One-time infra (streams/events are not device memory; created on the
    // eager correctness call, reused under capture as fork/join deps).
    static cudaStream_t s2 = nullptr;
    static cudaEvent_t evFork = nullptr, evJoin1 = nullptr, evG1 = nullptr, evJoin2 = nullptr;
    if (!s2) {
        cudaStreamCreateWithFlags(&s2, cudaStreamNonBlocking);
        cudaEventCreateWithFlags(&evFork,  cudaEventDisableTiming);
        cudaEventCreateWithFlags(&evJoin1, cudaEventDisableTiming);
        cudaEventCreateWithFlags(&evG1,    cudaEventDisableTiming);
        cudaEventCreateWithFlags(&evJoin2, cudaEventDisableTiming);
    }

    dim3 blk(256);
    const int gm = (NN + 127) / 128;  // 391

    // --- fork: CSR build + self1 GEMM on side stream, hidden behind rel1 GEMM ---
    cudaEventRecord(evFork, 0);
    cudaStreamWaitEvent(s2, evFork, 0);
    zero_cnt_kernel<<<(NN + 255) / 256, blk, 0, s2>>>(cnt);
    hist_kernel<<<(NE + 255) / 256, blk, 0, s2>>>(dst, cnt);
    scan_kernel<<<1, 1024, 0, s2>>>(cnt, off, cur);
    fill_kernel<<<(NE + 255) / 256, blk, 0, s2>>>(src, dst, et, cur, keys);
    gemm_f16x3<128, false, true, float><<<dim3(gm, 1, 1), blk, 0, s2>>>(feat, W1s, b1, h1);
    cudaEventRecord(evJoin1, s2);

    // Layer 1 (rel messages stored fp16)
    gemm_f16x3<128, false, false, __half><<<dim3(gm, 1, NR), blk>>>(feat, W1, nullptr, rel1);
    cudaStreamWaitEvent(0, evJoin1, 0);  // join: gather needs CSR + h1
    gather_h_kernel<128><<<(NN * 16 + 255) / 256, blk>>>(off, keys, rel1, h1);
    cudaEventRecord(evG1, 0);

    // Layer 2 (ReLU fused on reads of h1; rel2 fp16, L2-resident)
    cudaStreamWaitEvent(s2, evG1, 0);
    gemm_f16x3<64, true, true, float><<<dim3(gm, 1, 1), blk, 0, s2>>>(h1, W2s, b2, out);
    cudaEventRecord(evJoin2, s2);
    gemm_f16x3<64, true, false, __half><<<dim3(gm, 1, NR), blk>>>(h1, W2, nullptr, rel2);
    cudaStreamWaitEvent(0, evJoin2, 0);
    gather_h_kernel<64><<<(NN * 8 + 255) / 256, blk>>>(off, keys, rel2, out);
}